// round 6
// baseline (speedup 1.0000x reference)
#include <cuda_runtime.h>
#include <cuda_fp16.h>
#include <cstdint>

// ---------------- problem constants ----------------
#define E_      13
#define I_      13
#define H_      64
#define G_      256      // 4*H, torch gate order i,f,g,o
#define MT      256      // batch rows per tile (2 row-tiles per warp)
#define NTILES  24       // 192 gate-cols (i,g,o) / 8
#define THREADS 256      // 8 warps
#define TPC     8        // b-tiles per CTA

// ---------------- precomputed tables (built by prep kernel) ----------------
__device__ uint32_t g_bfrag[E_][NTILES * 64];   // f16x2 B fragments, smem image
__device__ uint32_t g_wl2[E_][32];              // packed W_lin pairs per (hc,tg)

// ---------------- helpers ----------------
static __device__ __forceinline__ uint32_t pack_f16x2(float lo, float hi) {
    uint32_t r;  // first asm src -> upper half
    asm("cvt.rn.f16x2.f32 %0, %1, %2;" : "=r"(r) : "f"(hi), "f"(lo));
    return r;
}
static __device__ __forceinline__ uint32_t tanh2(uint32_t v) {
    uint32_t y;
    asm("tanh.approx.f16x2 %0, %1;" : "=r"(y) : "r"(v));
    return y;
}
static __device__ __forceinline__ uint32_t hmul2(uint32_t a, uint32_t b) {
    uint32_t d;
    asm("mul.rn.f16x2 %0, %1, %2;" : "=r"(d) : "r"(a), "r"(b));
    return d;
}
static __device__ __forceinline__ uint32_t hfma2(uint32_t a, uint32_t b, uint32_t c) {
    uint32_t d;
    asm("fma.rn.f16x2 %0, %1, %2, %3;" : "=r"(d) : "r"(a), "r"(b), "r"(c));
    return d;
}
static __device__ __forceinline__ void unpack2(float& lo, float& hi, uint32_t v) {
    asm("{ .reg .b16 l, h;\n\t"
        "  mov.b32 {l, h}, %2;\n\t"
        "  cvt.f32.f16 %0, l;\n\t"
        "  cvt.f32.f16 %1, h; }"
        : "=f"(lo), "=f"(hi) : "r"(v));
}
#define H05 0x38003800u   // (0.5, 0.5) in f16x2

// f16-accumulate MMA: d0 = (row g, cols 2tg,2tg+1) packed, d1 = row g+8
#define MMA16816_F16(d0,d1, a0,a1,a2,a3, b0,b1)                                \
    asm volatile(                                                              \
        "mma.sync.aligned.m16n8k16.row.col.f16.f16.f16.f16 "                   \
        "{%0,%1}, {%2,%3,%4,%5}, {%6,%7}, {%0,%1};"                            \
        : "+r"(d0), "+r"(d1)                                                   \
        : "r"(a0), "r"(a1), "r"(a2), "r"(a3), "r"(b0), "r"(b1))

// ---------------- prep kernel: build per-e constant tables once ----------------
// Gate N-layout: 0-63 = i, 64-127 = g, 128-191 = o (f skipped: f*c0=0).
// i/o columns (and biases) PRE-SCALED by 0.5: sigma(x)=0.5*tanh(x/2)+0.5.
// K-layout (K=16): k 0-12 = W_ih, k 13 = b_ih+b_hh (ones-col), 14,15 = 0.
__global__ void prep_kernel(const float* __restrict__ Wih,
                            const float* __restrict__ bih,
                            const float* __restrict__ bhh,
                            const float* __restrict__ Wlin) {
    const int e = blockIdx.x, tid = threadIdx.x;
    for (int p = tid; p < NTILES * 32; p += THREADS) {
        int t  = p >> 5, ln = p & 31;
        int g  = ln >> 2, tg = ln & 3;
        int n  = t * 8 + g;
        int src = (n < 64) ? n : n + 64;              // i:0-63, g:128-191, o:192-255
        float scale = (n < 64 || n >= 128) ? 0.5f : 1.0f;
        const float* wrow = Wih + ((size_t)e * G_ + src) * I_;
        float bsum = (bih[e * G_ + src] + bhh[e * G_ + src]) * scale;
        float v[4];
        const int ks[4] = {2 * tg, 2 * tg + 1, 2 * tg + 8, 2 * tg + 9};
        #pragma unroll
        for (int j = 0; j < 4; j++) {
            int k = ks[j];
            v[j] = (k < I_) ? wrow[k] * scale : ((k == 13) ? bsum : 0.0f);
        }
        g_bfrag[e][p * 2 + 0] = pack_f16x2(v[0], v[1]);
        g_bfrag[e][p * 2 + 1] = pack_f16x2(v[2], v[3]);
    }
    if (tid < 32) {  // index = hc*4+tg
        int hc = tid >> 2, tg = tid & 3;
        g_wl2[e][tid] = pack_f16x2(Wlin[e * H_ + hc * 8 + 2 * tg],
                                   Wlin[e * H_ + hc * 8 + 2 * tg + 1]);
    }
}

// ---------------- main kernel ----------------
// Grid (E, (B/MT)/TPC) = (13, 64). Each CTA: 8 consecutive 256-row tiles of one e.
// Software pipeline: while computing tile t from smem, tile t+1's x is already
// in flight into registers (issued before the barrier).
__global__ __launch_bounds__(THREADS) void MusicLSTM_kernel(
    const float* __restrict__ x,      // [B, E, I]
    const float* __restrict__ blin,   // [E]
    float* __restrict__ out)          // [B, E]
{
    __shared__ uint32_t xs[MT * 8];          // packed f16x2, [row][slot 0..7]
    __shared__ uint32_t bsm[NTILES * 64];    // B fragments
    __shared__ uint32_t wsm[32];             // packed W_lin pairs

    const int tid = threadIdx.x;
    const int e   = blockIdx.x;

    // ---- load prebuilt tables once per CTA (coalesced) ----
    {
        const uint4* src = (const uint4*)g_bfrag[e];
        uint4* dst = (uint4*)bsm;
        dst[tid] = src[tid];                              // 256 * 16B
        if (tid < 128) dst[256 + tid] = src[256 + tid];   // remaining 128
        if (tid < 32) wsm[tid] = g_wl2[e][tid];
    }

    // ---- fixed per-thread staging role: slot s, rows rbase+32i ----
    const int s     = tid & 7;
    const int rbase = tid >> 3;
    const size_t rowstride  = (size_t)(E_ * I_);          // floats per batch row
    const size_t tilestride = (size_t)MT * rowstride;     // floats per tile

    // thread's row-0 pointer for tile 0 of this CTA
    const float* gx = x + ((size_t)blockIdx.y * TPC * MT + rbase) * rowstride + e * I_;

    // compute-side ids
    const int ln = tid & 31, wid = tid >> 5;
    const int g  = ln >> 2,  tg = ln & 3;
    const int r0 = wid * 16;
    const float bl = __ldg(&blin[e]);

    // ---- prefetch tile 0 into registers ----
    float P[16];
    #pragma unroll
    for (int i = 0; i < 8; i++) {
        const float* row = gx + (size_t)(32 * i) * rowstride;
        if (s < 6)       { P[2 * i] = row[2 * s]; P[2 * i + 1] = row[2 * s + 1]; }
        else if (s == 6) { P[2 * i] = row[12]; }
    }

    #pragma unroll 1
    for (int t = 0; t < TPC; t++) {
        __syncthreads();   // previous compute done reading xs (no-op cost at t=0)

        // ---- store prefetched tile into smem (pack to f16x2 here) ----
        #pragma unroll
        for (int i = 0; i < 8; i++) {
            uint32_t v;
            if (s < 6)       v = pack_f16x2(P[2 * i], P[2 * i + 1]);
            else if (s == 6) v = pack_f16x2(P[2 * i], 1.0f);
            else             v = 0u;
            xs[(rbase + 32 * i) * 8 + s] = v;
        }

        // ---- issue LDGs for next tile (latency hidden under compute below) ----
        if (t + 1 < TPC) {
            const float* gnext = gx + (size_t)(t + 1) * tilestride;
            #pragma unroll
            for (int i = 0; i < 8; i++) {
                const float* row = gnext + (size_t)(32 * i) * rowstride;
                if (s < 6)       { P[2 * i] = row[2 * s]; P[2 * i + 1] = row[2 * s + 1]; }
                else if (s == 6) { P[2 * i] = row[12]; }
            }
        }
        __syncthreads();

        // ---- A fragments for both row-tiles (pure LDS.32) ----
        uint32_t raA0 = xs[(r0 + g)           * 8 + tg];
        uint32_t raA1 = xs[(r0 + g + 8)       * 8 + tg];
        uint32_t raA2 = xs[(r0 + g)           * 8 + tg + 4];
        uint32_t raA3 = xs[(r0 + g + 8)       * 8 + tg + 4];
        uint32_t raB0 = xs[(r0 + 128 + g)     * 8 + tg];
        uint32_t raB1 = xs[(r0 + 128 + g + 8) * 8 + tg];
        uint32_t raB2 = xs[(r0 + 128 + g)     * 8 + tg + 4];
        uint32_t raB3 = xs[(r0 + 128 + g + 8) * 8 + tg + 4];

        uint32_t accA0 = 0u, accB0 = 0u;   // tile0: rows g, g+8 (f16x2 pairs)
        uint32_t accA1 = 0u, accB1 = 0u;   // tile1

        #pragma unroll
        for (int hc = 0; hc < 8; hc++) {
            uint2 bi = *(const uint2*)&bsm[(hc)      * 64 + ln * 2];
            uint2 bg = *(const uint2*)&bsm[(hc + 8)  * 64 + ln * 2];
            uint2 bo = *(const uint2*)&bsm[(hc + 16) * 64 + ln * 2];
            uint32_t w2 = wsm[hc * 4 + tg];

            {   // row-tile 0
                uint32_t di0 = 0, di1 = 0, dg0 = 0, dg1 = 0, dq0 = 0, dq1 = 0;
                MMA16816_F16(di0, di1, raA0, raA1, raA2, raA3, bi.x, bi.y);
                MMA16816_F16(dg0, dg1, raA0, raA1, raA2, raA3, bg.x, bg.y);
                MMA16816_F16(dq0, dq1, raA0, raA1, raA2, raA3, bo.x, bo.y);
                uint32_t si0 = hfma2(tanh2(di0), H05, H05);
                uint32_t si1 = hfma2(tanh2(di1), H05, H05);
                uint32_t tg0 = tanh2(dg0);
                uint32_t tg1 = tanh2(dg1);
                uint32_t so0 = hfma2(tanh2(dq0), H05, H05);
                uint32_t so1 = hfma2(tanh2(dq1), H05, H05);
                uint32_t h0 = hmul2(so0, tanh2(hmul2(si0, tg0)));
                uint32_t h1 = hmul2(so1, tanh2(hmul2(si1, tg1)));
                accA0 = hfma2(h0, w2, accA0);
                accB0 = hfma2(h1, w2, accB0);
            }
            {   // row-tile 1
                uint32_t di0 = 0, di1 = 0, dg0 = 0, dg1 = 0, dq0 = 0, dq1 = 0;
                MMA16816_F16(di0, di1, raB0, raB1, raB2, raB3, bi.x, bi.y);
                MMA16816_F16(dg0, dg1, raB0, raB1, raB2, raB3, bg.x, bg.y);
                MMA16816_F16(dq0, dq1, raB0, raB1, raB2, raB3, bo.x, bo.y);
                uint32_t si0 = hfma2(tanh2(di0), H05, H05);
                uint32_t si1 = hfma2(tanh2(di1), H05, H05);
                uint32_t tg0 = tanh2(dg0);
                uint32_t tg1 = tanh2(dg1);
                uint32_t so0 = hfma2(tanh2(dq0), H05, H05);
                uint32_t so1 = hfma2(tanh2(dq1), H05, H05);
                uint32_t h0 = hmul2(so0, tanh2(hmul2(si0, tg0)));
                uint32_t h1 = hmul2(so1, tanh2(hmul2(si1, tg1)));
                accA1 = hfma2(h0, w2, accA1);
                accB1 = hfma2(h1, w2, accB1);
            }
        }

        // ---- tail: f32 finish ----
        float lo, hi;
        unpack2(lo, hi, accA0); float zA0 = lo + hi;
        unpack2(lo, hi, accB0); float zB0 = lo + hi;
        unpack2(lo, hi, accA1); float zA1 = lo + hi;
        unpack2(lo, hi, accB1); float zB1 = lo + hi;

        zA0 += __shfl_xor_sync(0xffffffffu, zA0, 1);
        zA0 += __shfl_xor_sync(0xffffffffu, zA0, 2);
        zB0 += __shfl_xor_sync(0xffffffffu, zB0, 1);
        zB0 += __shfl_xor_sync(0xffffffffu, zB0, 2);
        zA1 += __shfl_xor_sync(0xffffffffu, zA1, 1);
        zA1 += __shfl_xor_sync(0xffffffffu, zA1, 2);
        zB1 += __shfl_xor_sync(0xffffffffu, zB1, 1);
        zB1 += __shfl_xor_sync(0xffffffffu, zB1, 2);

        if (tg == 0) {
            int b0 = ((int)blockIdx.y * TPC + t) * MT;
            size_t base = (size_t)(b0 + r0 + g) * E_ + e;
            out[base]            = __fdividef(1.f, 1.f + __expf(-(zA0 + bl)));
            out[base + 8 * E_]   = __fdividef(1.f, 1.f + __expf(-(zB0 + bl)));
            out[base + 128 * E_] = __fdividef(1.f, 1.f + __expf(-(zA1 + bl)));
            out[base + 136 * E_] = __fdividef(1.f, 1.f + __expf(-(zB1 + bl)));
        }
    }
}

// ---------------- launch ----------------
extern "C" void kernel_launch(void* const* d_in, const int* in_sizes, int n_in,
                              void* d_out, int out_size) {
    const float* x    = (const float*)d_in[0];
    const float* Wih  = (const float*)d_in[1];
    // d_in[2] = W_hh multiplies h0 = 0 -> unused
    const float* bih  = (const float*)d_in[3];
    const float* bhh  = (const float*)d_in[4];
    const float* Wlin = (const float*)d_in[5];
    const float* blin = (const float*)d_in[6];
    float* out = (float*)d_out;

    int Bv = in_sizes[0] / (E_ * I_);    // 131072
    prep_kernel<<<E_, THREADS>>>(Wih, bih, bhh, Wlin);
    dim3 grid(E_, Bv / (MT * TPC));      // (13, 64)
    MusicLSTM_kernel<<<grid, THREADS>>>(x, blin, out);
}

// round 7
// speedup vs baseline: 1.1777x; 1.1777x over previous
#include <cuda_runtime.h>
#include <cuda_fp16.h>
#include <cstdint>

// ---------------- problem constants ----------------
#define E_      13
#define I_      13
#define H_      64
#define G_      256      // 4*H, torch gate order i,f,g,o
#define MT      256      // batch rows per CTA (2 row-tiles per warp)
#define NTILES  24       // 192 gate-cols (i,g,o) / 8
#define THREADS 256      // 8 warps
#define ROWF    (E_ * I_)  // 169 floats per batch row

// ---------------- precomputed tables (built by prep kernel) ----------------
__device__ uint32_t g_bfrag[E_][NTILES * 64];   // f16x2 B fragments, smem image
__device__ uint32_t g_wl2[E_][32];              // packed W_lin pairs per (hc,tg)

// ---------------- helpers ----------------
static __device__ __forceinline__ uint32_t pack_f16x2(float lo, float hi) {
    uint32_t r;  // first asm src -> upper half
    asm("cvt.rn.f16x2.f32 %0, %1, %2;" : "=r"(r) : "f"(hi), "f"(lo));
    return r;
}
static __device__ __forceinline__ uint32_t tanh2(uint32_t v) {
    uint32_t y;
    asm("tanh.approx.f16x2 %0, %1;" : "=r"(y) : "r"(v));
    return y;
}
static __device__ __forceinline__ uint32_t hmul2(uint32_t a, uint32_t b) {
    uint32_t d;
    asm("mul.rn.f16x2 %0, %1, %2;" : "=r"(d) : "r"(a), "r"(b));
    return d;
}
static __device__ __forceinline__ uint32_t hfma2(uint32_t a, uint32_t b, uint32_t c) {
    uint32_t d;
    asm("fma.rn.f16x2 %0, %1, %2, %3;" : "=r"(d) : "r"(a), "r"(b), "r"(c));
    return d;
}
static __device__ __forceinline__ void unpack2(float& lo, float& hi, uint32_t v) {
    asm("{ .reg .b16 l, h;\n\t"
        "  mov.b32 {l, h}, %2;\n\t"
        "  cvt.f32.f16 %0, l;\n\t"
        "  cvt.f32.f16 %1, h; }"
        : "=f"(lo), "=f"(hi) : "r"(v));
}
#define H05 0x38003800u   // (0.5, 0.5) in f16x2

// f16-accumulate MMA: d0 = (row g, cols 2tg,2tg+1) packed, d1 = row g+8
#define MMA16816_F16(d0,d1, a0,a1,a2,a3, b0,b1)                                \
    asm volatile(                                                              \
        "mma.sync.aligned.m16n8k16.row.col.f16.f16.f16.f16 "                   \
        "{%0,%1}, {%2,%3,%4,%5}, {%6,%7}, {%0,%1};"                            \
        : "+r"(d0), "+r"(d1)                                                   \
        : "r"(a0), "r"(a1), "r"(a2), "r"(a3), "r"(b0), "r"(b1))

// ---------------- prep kernel: build per-e constant tables once ----------------
// Gate N-layout: 0-63 = i, 64-127 = g, 128-191 = o (f skipped: f*c0=0).
// i/o columns (and biases) PRE-SCALED by 0.5: sigma(x)=0.5*tanh(x/2)+0.5.
// K-layout (K=16): k 0-12 = W_ih, k 13 = b_ih+b_hh (ones-col), 14,15 = 0.
__global__ void prep_kernel(const float* __restrict__ Wih,
                            const float* __restrict__ bih,
                            const float* __restrict__ bhh,
                            const float* __restrict__ Wlin) {
    const int e = blockIdx.x, tid = threadIdx.x;
    for (int p = tid; p < NTILES * 32; p += THREADS) {
        int t  = p >> 5, ln = p & 31;
        int g  = ln >> 2, tg = ln & 3;
        int n  = t * 8 + g;
        int src = (n < 64) ? n : n + 64;              // i:0-63, g:128-191, o:192-255
        float scale = (n < 64 || n >= 128) ? 0.5f : 1.0f;
        const float* wrow = Wih + ((size_t)e * G_ + src) * I_;
        float bsum = (bih[e * G_ + src] + bhh[e * G_ + src]) * scale;
        float v[4];
        const int ks[4] = {2 * tg, 2 * tg + 1, 2 * tg + 8, 2 * tg + 9};
        #pragma unroll
        for (int j = 0; j < 4; j++) {
            int k = ks[j];
            v[j] = (k < I_) ? wrow[k] * scale : ((k == 13) ? bsum : 0.0f);
        }
        g_bfrag[e][p * 2 + 0] = pack_f16x2(v[0], v[1]);
        g_bfrag[e][p * 2 + 1] = pack_f16x2(v[2], v[3]);
    }
    if (tid < 32) {  // index = hc*4+tg
        int hc = tid >> 2, tg = tid & 3;
        g_wl2[e][tid] = pack_f16x2(Wlin[e * H_ + hc * 8 + 2 * tg],
                                   Wlin[e * H_ + hc * 8 + 2 * tg + 1]);
    }
}

// ---------------- main kernel ----------------
// Grid (E, B/256), e fastest. Warp w owns rows [b0+16w,+16) and [b0+128+16w,+16).
// NO x smem tile, NO per-tile barriers: each lane LDGs exactly its own
// A-fragment floats. Single barrier for the B-table stage only.
__global__ __launch_bounds__(THREADS) void MusicLSTM_kernel(
    const float* __restrict__ x,      // [B, E, I]
    const float* __restrict__ blin,   // [E]
    float* __restrict__ out)          // [B, E]
{
    __shared__ uint32_t bsm[NTILES * 64];    // B fragments
    __shared__ uint32_t wsm[32];             // packed W_lin pairs

    const int tid = threadIdx.x;
    const int e   = blockIdx.x;
    const int b0  = blockIdx.y * MT;

    // ---- load prebuilt tables once (coalesced) ----
    {
        const uint4* src = (const uint4*)g_bfrag[e];
        uint4* dst = (uint4*)bsm;
        dst[tid] = src[tid];                              // 256 * 16B
        if (tid < 128) dst[256 + tid] = src[256 + tid];   // remaining 128
        if (tid < 32) wsm[tid] = g_wl2[e][tid];
    }

    const int ln = tid & 31, wid = tid >> 5;
    const int g  = ln >> 2,  tg = ln & 3;
    const int r0 = wid * 16;

    // ---- A fragments straight from global (per-lane mapping) ----
    // a0 = (row, k 2tg..2tg+1), a1 = row+8 same k, a2 = (row, k 2tg+8..2tg+9),
    // a3 = row+8 same. k=13 is the ones/bias column -> tg==2 hi-half = 1.0;
    // k=14,15 -> tg==3 second pair = 0.
    const float* rA  = x + (size_t)(b0 + r0 + g)       * ROWF + e * I_;
    const float* rA8 = x + (size_t)(b0 + r0 + g + 8)   * ROWF + e * I_;
    const float* rB  = x + (size_t)(b0 + r0 + g + 128) * ROWF + e * I_;
    const float* rB8 = x + (size_t)(b0 + r0 + g + 136) * ROWF + e * I_;

    uint32_t raA0 = pack_f16x2(rA [2 * tg], rA [2 * tg + 1]);
    uint32_t raA1 = pack_f16x2(rA8[2 * tg], rA8[2 * tg + 1]);
    uint32_t raB0 = pack_f16x2(rB [2 * tg], rB [2 * tg + 1]);
    uint32_t raB1 = pack_f16x2(rB8[2 * tg], rB8[2 * tg + 1]);
    uint32_t raA2, raA3, raB2, raB3;
    if (tg < 2) {
        raA2 = pack_f16x2(rA [2 * tg + 8], rA [2 * tg + 9]);
        raA3 = pack_f16x2(rA8[2 * tg + 8], rA8[2 * tg + 9]);
        raB2 = pack_f16x2(rB [2 * tg + 8], rB [2 * tg + 9]);
        raB3 = pack_f16x2(rB8[2 * tg + 8], rB8[2 * tg + 9]);
    } else if (tg == 2) {   // k = 12, 13 (ones column)
        raA2 = pack_f16x2(rA [12], 1.0f);
        raA3 = pack_f16x2(rA8[12], 1.0f);
        raB2 = pack_f16x2(rB [12], 1.0f);
        raB3 = pack_f16x2(rB8[12], 1.0f);
    } else {                 // k = 14, 15 -> zero pad
        raA2 = raA3 = raB2 = raB3 = 0u;
    }

    __syncthreads();   // bsm/wsm ready

    uint32_t accA0 = 0u, accB0 = 0u;   // tile0: rows g, g+8 (f16x2 pairs)
    uint32_t accA1 = 0u, accB1 = 0u;   // tile1

    #pragma unroll
    for (int hc = 0; hc < 8; hc++) {
        uint2 bi = *(const uint2*)&bsm[(hc)      * 64 + ln * 2];
        uint2 bg = *(const uint2*)&bsm[(hc + 8)  * 64 + ln * 2];
        uint2 bo = *(const uint2*)&bsm[(hc + 16) * 64 + ln * 2];
        uint32_t w2 = wsm[hc * 4 + tg];

        {   // row-tile 0
            uint32_t di0 = 0, di1 = 0, dg0 = 0, dg1 = 0, dq0 = 0, dq1 = 0;
            MMA16816_F16(di0, di1, raA0, raA1, raA2, raA3, bi.x, bi.y);
            MMA16816_F16(dg0, dg1, raA0, raA1, raA2, raA3, bg.x, bg.y);
            MMA16816_F16(dq0, dq1, raA0, raA1, raA2, raA3, bo.x, bo.y);
            uint32_t si0 = hfma2(tanh2(di0), H05, H05);
            uint32_t si1 = hfma2(tanh2(di1), H05, H05);
            uint32_t tg0 = tanh2(dg0);
            uint32_t tg1 = tanh2(dg1);
            uint32_t so0 = hfma2(tanh2(dq0), H05, H05);
            uint32_t so1 = hfma2(tanh2(dq1), H05, H05);
            uint32_t h0 = hmul2(so0, tanh2(hmul2(si0, tg0)));
            uint32_t h1 = hmul2(so1, tanh2(hmul2(si1, tg1)));
            accA0 = hfma2(h0, w2, accA0);
            accB0 = hfma2(h1, w2, accB0);
        }
        {   // row-tile 1
            uint32_t di0 = 0, di1 = 0, dg0 = 0, dg1 = 0, dq0 = 0, dq1 = 0;
            MMA16816_F16(di0, di1, raB0, raB1, raB2, raB3, bi.x, bi.y);
            MMA16816_F16(dg0, dg1, raB0, raB1, raB2, raB3, bg.x, bg.y);
            MMA16816_F16(dq0, dq1, raB0, raB1, raB2, raB3, bo.x, bo.y);
            uint32_t si0 = hfma2(tanh2(di0), H05, H05);
            uint32_t si1 = hfma2(tanh2(di1), H05, H05);
            uint32_t tg0 = tanh2(dg0);
            uint32_t tg1 = tanh2(dg1);
            uint32_t so0 = hfma2(tanh2(dq0), H05, H05);
            uint32_t so1 = hfma2(tanh2(dq1), H05, H05);
            uint32_t h0 = hmul2(so0, tanh2(hmul2(si0, tg0)));
            uint32_t h1 = hmul2(so1, tanh2(hmul2(si1, tg1)));
            accA1 = hfma2(h0, w2, accA1);
            accB1 = hfma2(h1, w2, accB1);
        }
    }

    // ---- tail: f32 finish ----
    float lo, hi;
    unpack2(lo, hi, accA0); float zA0 = lo + hi;
    unpack2(lo, hi, accB0); float zB0 = lo + hi;
    unpack2(lo, hi, accA1); float zA1 = lo + hi;
    unpack2(lo, hi, accB1); float zB1 = lo + hi;

    zA0 += __shfl_xor_sync(0xffffffffu, zA0, 1);
    zA0 += __shfl_xor_sync(0xffffffffu, zA0, 2);
    zB0 += __shfl_xor_sync(0xffffffffu, zB0, 1);
    zB0 += __shfl_xor_sync(0xffffffffu, zB0, 2);
    zA1 += __shfl_xor_sync(0xffffffffu, zA1, 1);
    zA1 += __shfl_xor_sync(0xffffffffu, zA1, 2);
    zB1 += __shfl_xor_sync(0xffffffffu, zB1, 1);
    zB1 += __shfl_xor_sync(0xffffffffu, zB1, 2);

    if (tg == 0) {
        float bl = __ldg(&blin[e]);
        size_t base = (size_t)(b0 + r0 + g) * E_ + e;
        out[base]            = __fdividef(1.f, 1.f + __expf(-(zA0 + bl)));
        out[base + 8 * E_]   = __fdividef(1.f, 1.f + __expf(-(zB0 + bl)));
        out[base + 128 * E_] = __fdividef(1.f, 1.f + __expf(-(zA1 + bl)));
        out[base + 136 * E_] = __fdividef(1.f, 1.f + __expf(-(zB1 + bl)));
    }
}

// ---------------- launch ----------------
extern "C" void kernel_launch(void* const* d_in, const int* in_sizes, int n_in,
                              void* d_out, int out_size) {
    const float* x    = (const float*)d_in[0];
    const float* Wih  = (const float*)d_in[1];
    // d_in[2] = W_hh multiplies h0 = 0 -> unused
    const float* bih  = (const float*)d_in[3];
    const float* bhh  = (const float*)d_in[4];
    const float* Wlin = (const float*)d_in[5];
    const float* blin = (const float*)d_in[6];
    float* out = (float*)d_out;

    int Bv = in_sizes[0] / (E_ * I_);    // 131072
    prep_kernel<<<E_, THREADS>>>(Wih, bih, bhh, Wlin);
    dim3 grid(E_, Bv / MT);              // (13, 512)
    MusicLSTM_kernel<<<grid, THREADS>>>(x, blin, out);
}